// round 10
// baseline (speedup 1.0000x reference)
#include <cuda_runtime.h>
#include <cstdint>

// ---------------------------------------------------------------------------
// HeteroGraphConv, D=128.
//   CSR preprocess (side stream): hist -> 3-stage scan -> fill (int2 edges)
//   per direction (own stream):
//     T = (relu(x@w1+b1))@w2+b2            (fused tf32 mma kernel, smem H)
//     out = relu(LN((x+gather)@wu+bu)*g+be) (ONE fused kernel: CSR gather ->
//                                            smem A-tile -> MMA -> LN)
// ---------------------------------------------------------------------------

#define D128 128
#define MAXN 50176
#define MAXE 450048

__device__ float g_T0[MAXN * D128];
__device__ float g_T1[MAXN * D128];
__device__ int   g_cnt [2][MAXN];
__device__ int   g_off [2][MAXN + 1];
__device__ int   g_bsum[2][64];
__device__ int2  g_edge[2][MAXE];

__device__ __forceinline__ unsigned f2tf32(float f) {
    unsigned r;
    asm("cvt.rna.tf32.f32 %0, %1;" : "=r"(r) : "f"(f));
    return r;
}
__device__ __forceinline__ float tf32f(float f) { return __uint_as_float(f2tf32(f)); }

#define TS 132
#define TILE (128 * TS)
#define MLP_SMEM (3 * TILE * sizeof(float))
#define GLN_SMEM (2 * TILE * sizeof(float))

// ---------------------------------------------------------------------------
// Shared MMA mainloop: 16 warps (4x4), warp (wm,wn) owns 32x32 output tile.
// Am, Bm: [128][TS] tf32-in-float smem tiles. acc[2][4][4] += Am @ Bm.
// ---------------------------------------------------------------------------
__device__ __forceinline__ void mma_mainloop_128(
    const float* Am, const float* Bm,
    int wm, int wn, int g, int t, float acc[2][4][4])
{
    #pragma unroll
    for (int ks = 0; ks < 16; ks++) {
        const int k0 = ks * 8;
        unsigned a[2][4];
        #pragma unroll
        for (int mf = 0; mf < 2; mf++) {
            const float* ap = Am + (wm * 32 + mf * 16 + g) * TS + k0 + t;
            a[mf][0] = __float_as_uint(ap[0]);
            a[mf][1] = __float_as_uint(ap[8 * TS]);
            a[mf][2] = __float_as_uint(ap[4]);
            a[mf][3] = __float_as_uint(ap[8 * TS + 4]);
        }
        unsigned b[4][2];
        #pragma unroll
        for (int nf = 0; nf < 4; nf++) {
            const float* wp = Bm + (k0 + t) * TS + wn * 32 + nf * 8 + g;
            b[nf][0] = __float_as_uint(wp[0]);
            b[nf][1] = __float_as_uint(wp[4 * TS]);
        }
        #pragma unroll
        for (int mf = 0; mf < 2; mf++)
            #pragma unroll
            for (int nf = 0; nf < 4; nf++)
                asm volatile(
                    "mma.sync.aligned.m16n8k8.row.col.f32.tf32.tf32.f32 "
                    "{%0,%1,%2,%3}, {%4,%5,%6,%7}, {%8,%9}, {%0,%1,%2,%3};"
                    : "+f"(acc[mf][nf][0]), "+f"(acc[mf][nf][1]),
                      "+f"(acc[mf][nf][2]), "+f"(acc[mf][nf][3])
                    : "r"(a[mf][0]), "r"(a[mf][1]), "r"(a[mf][2]), "r"(a[mf][3]),
                      "r"(b[nf][0]), "r"(b[nf][1]));
    }
}

// ---------------------------------------------------------------------------
// Fused edge-MLP: T[M,128] = relu(A@W1+b1)@W2+b2 (smem-resident H).
// ---------------------------------------------------------------------------
__global__ __launch_bounds__(512)
void mlp_fused(const float* __restrict__ A,
               const float* __restrict__ W1, const float* __restrict__ b1,
               const float* __restrict__ W2, const float* __restrict__ b2,
               float* __restrict__ T, int M)
{
    extern __shared__ float smem[];
    float* X  = smem;
    float* Wb = smem + TILE;
    float* Ht = smem + 2 * TILE;

    const int tid  = threadIdx.x;
    const int lane = tid & 31;
    const int wid  = tid >> 5;
    const int wm   = wid >> 2;
    const int wn   = wid & 3;
    const int g    = lane >> 2;
    const int t    = lane & 3;
    const int row0 = blockIdx.x * 128;

    #pragma unroll
    for (int i = 0; i < 8; i++) {
        int idx = tid + i * 512, r = idx >> 5, c = (idx & 31) * 4;
        int gr = row0 + r;
        float4 v = (gr < M) ? *reinterpret_cast<const float4*>(A + (size_t)gr * D128 + c)
                            : make_float4(0.f, 0.f, 0.f, 0.f);
        float4 w = *reinterpret_cast<const float4*>(W1 + (size_t)r * D128 + c);
        *reinterpret_cast<float4*>(X + r * TS + c) =
            make_float4(tf32f(v.x), tf32f(v.y), tf32f(v.z), tf32f(v.w));
        *reinterpret_cast<float4*>(Wb + r * TS + c) =
            make_float4(tf32f(w.x), tf32f(w.y), tf32f(w.z), tf32f(w.w));
    }
    __syncthreads();

    float acc[2][4][4];
    #pragma unroll
    for (int mf = 0; mf < 2; mf++)
        #pragma unroll
        for (int nf = 0; nf < 4; nf++)
            #pragma unroll
            for (int j = 0; j < 4; j++) acc[mf][nf][j] = 0.0f;

    // Phase 1: H = relu(X@W1 + b1) -> Ht (tf32)
    mma_mainloop_128(X, Wb, wm, wn, g, t, acc);
    #pragma unroll
    for (int mf = 0; mf < 2; mf++) {
        int r_ = wm * 32 + mf * 16 + g;
        #pragma unroll
        for (int nf = 0; nf < 4; nf++) {
            int col = wn * 32 + nf * 8 + 2 * t;
            float b0 = b1[col], b1v = b1[col + 1];
            Ht[r_ * TS + col]           = tf32f(fmaxf(acc[mf][nf][0] + b0,  0.f));
            Ht[r_ * TS + col + 1]       = tf32f(fmaxf(acc[mf][nf][1] + b1v, 0.f));
            Ht[(r_ + 8) * TS + col]     = tf32f(fmaxf(acc[mf][nf][2] + b0,  0.f));
            Ht[(r_ + 8) * TS + col + 1] = tf32f(fmaxf(acc[mf][nf][3] + b1v, 0.f));
            acc[mf][nf][0] = acc[mf][nf][1] = acc[mf][nf][2] = acc[mf][nf][3] = 0.f;
        }
    }
    __syncthreads();

    // Swap W2 into Wb.
    #pragma unroll
    for (int i = 0; i < 8; i++) {
        int idx = tid + i * 512, r = idx >> 5, c = (idx & 31) * 4;
        float4 w = *reinterpret_cast<const float4*>(W2 + (size_t)r * D128 + c);
        *reinterpret_cast<float4*>(Wb + r * TS + c) =
            make_float4(tf32f(w.x), tf32f(w.y), tf32f(w.z), tf32f(w.w));
    }
    __syncthreads();

    // Phase 2: T = Ht@W2 + b2
    mma_mainloop_128(Ht, Wb, wm, wn, g, t, acc);
    #pragma unroll
    for (int mf = 0; mf < 2; mf++) {
        int r_ = row0 + wm * 32 + mf * 16 + g;
        #pragma unroll
        for (int nf = 0; nf < 4; nf++) {
            int col = wn * 32 + nf * 8 + 2 * t;
            float b0 = b2[col], b1v = b2[col + 1];
            float2 v0, v1;
            v0.x = acc[mf][nf][0] + b0; v0.y = acc[mf][nf][1] + b1v;
            v1.x = acc[mf][nf][2] + b0; v1.y = acc[mf][nf][3] + b1v;
            if (r_ < M)
                *reinterpret_cast<float2*>(T + (size_t)r_ * D128 + col) = v0;
            if (r_ + 8 < M)
                *reinterpret_cast<float2*>(T + (size_t)(r_ + 8) * D128 + col) = v1;
        }
    }
}

// ---------------------------------------------------------------------------
// Fused gather + node-update GEMM + LayerNorm + ReLU.
// Phase 0: warp w gathers rows w*8..w*8+7: acc = x[row] + sum w_e*T[src_e],
//          tf32-converted straight into smem A-tile X.
// Phase 1: MMA mainloop X @ Wu.
// Phase 2: LN epilogue (S tile reuses X), single write to out.
// smem: X[128][132] | Wb[128][132]  (135 KB)
// ---------------------------------------------------------------------------
__global__ __launch_bounds__(512)
void gather_gemm_ln(const float* __restrict__ T,
                    const float* __restrict__ x,
                    const int* __restrict__ off,
                    const int2* __restrict__ edge,
                    const float* __restrict__ Wu,
                    const float* __restrict__ bias,
                    const float* __restrict__ gamma,
                    const float* __restrict__ beta,
                    float* __restrict__ C,
                    int M)
{
    extern __shared__ float smem[];
    float* X  = smem;
    float* Wb = smem + TILE;

    const int tid  = threadIdx.x;
    const int lane = tid & 31;
    const int wid  = tid >> 5;
    const int wm   = wid >> 2;
    const int wn   = wid & 3;
    const int g    = lane >> 2;
    const int t    = lane & 3;
    const int row0 = blockIdx.x * 128;

    // Load Wu tile (all 512 threads).
    #pragma unroll
    for (int i = 0; i < 8; i++) {
        int idx = tid + i * 512, r = idx >> 5, c = (idx & 31) * 4;
        float4 w = *reinterpret_cast<const float4*>(Wu + (size_t)r * D128 + c);
        *reinterpret_cast<float4*>(Wb + r * TS + c) =
            make_float4(tf32f(w.x), tf32f(w.y), tf32f(w.z), tf32f(w.w));
    }

    // Phase 0: gather. Warp wid handles rows wid*8 .. wid*8+7.
    #pragma unroll
    for (int rr = 0; rr < 8; rr++) {
        int r  = wid * 8 + rr;
        int gr = row0 + r;
        float4 acc;
        if (gr < M) {
            acc = reinterpret_cast<const float4*>(x + (size_t)gr * D128)[lane];
            int j  = __ldg(off + gr);
            int s1 = __ldg(off + gr + 1);
            for (; j + 1 < s1; j += 2) {
                int2 eA = __ldg(edge + j), eB = __ldg(edge + j + 1);
                float wA = __int_as_float(eA.y), wB = __int_as_float(eB.y);
                float4 vA = reinterpret_cast<const float4*>(T + (size_t)eA.x * D128)[lane];
                float4 vB = reinterpret_cast<const float4*>(T + (size_t)eB.x * D128)[lane];
                acc.x = fmaf(wA, vA.x, acc.x); acc.x = fmaf(wB, vB.x, acc.x);
                acc.y = fmaf(wA, vA.y, acc.y); acc.y = fmaf(wB, vB.y, acc.y);
                acc.z = fmaf(wA, vA.z, acc.z); acc.z = fmaf(wB, vB.z, acc.z);
                acc.w = fmaf(wA, vA.w, acc.w); acc.w = fmaf(wB, vB.w, acc.w);
            }
            if (j < s1) {
                int2 eA = __ldg(edge + j);
                float wA = __int_as_float(eA.y);
                float4 vA = reinterpret_cast<const float4*>(T + (size_t)eA.x * D128)[lane];
                acc.x = fmaf(wA, vA.x, acc.x);
                acc.y = fmaf(wA, vA.y, acc.y);
                acc.z = fmaf(wA, vA.z, acc.z);
                acc.w = fmaf(wA, vA.w, acc.w);
            }
        } else {
            acc = make_float4(0.f, 0.f, 0.f, 0.f);
        }
        *reinterpret_cast<float4*>(X + r * TS + lane * 4) =
            make_float4(tf32f(acc.x), tf32f(acc.y), tf32f(acc.z), tf32f(acc.w));
    }
    __syncthreads();

    // Phase 1: MMA.
    float acc[2][4][4];
    #pragma unroll
    for (int mf = 0; mf < 2; mf++)
        #pragma unroll
        for (int nf = 0; nf < 4; nf++)
            #pragma unroll
            for (int j = 0; j < 4; j++) acc[mf][nf][j] = 0.0f;

    mma_mainloop_128(X, Wb, wm, wn, g, t, acc);
    __syncthreads();   // X fully consumed; safe to reuse as S

    // Phase 2: LN epilogue. S = X tile.
    float* S = X;
    #pragma unroll
    for (int mf = 0; mf < 2; mf++) {
        int r_ = wm * 32 + mf * 16 + g;
        #pragma unroll
        for (int nf = 0; nf < 4; nf++) {
            int col = wn * 32 + nf * 8 + 2 * t;
            S[r_ * TS + col]           = acc[mf][nf][0];
            S[r_ * TS + col + 1]       = acc[mf][nf][1];
            S[(r_ + 8) * TS + col]     = acc[mf][nf][2];
            S[(r_ + 8) * TS + col + 1] = acc[mf][nf][3];
        }
    }
    __syncthreads();

    float4 bv = *reinterpret_cast<const float4*>(bias  + lane * 4);
    float4 gv = *reinterpret_cast<const float4*>(gamma + lane * 4);
    float4 ev = *reinterpret_cast<const float4*>(beta  + lane * 4);

    #pragma unroll
    for (int rr = 0; rr < 8; rr++) {
        int r_ = wid * 8 + rr;
        float4 h = *reinterpret_cast<const float4*>(S + r_ * TS + lane * 4);
        h.x += bv.x; h.y += bv.y; h.z += bv.z; h.w += bv.w;
        float s = h.x + h.y + h.z + h.w;
        #pragma unroll
        for (int o = 16; o > 0; o >>= 1) s += __shfl_xor_sync(0xFFFFFFFFu, s, o);
        float mu = s * (1.0f / 128.0f);
        float d0 = h.x - mu, d1 = h.y - mu, d2 = h.z - mu, d3 = h.w - mu;
        float q = d0 * d0 + d1 * d1 + d2 * d2 + d3 * d3;
        #pragma unroll
        for (int o = 16; o > 0; o >>= 1) q += __shfl_xor_sync(0xFFFFFFFFu, q, o);
        float rstd = rsqrtf(q * (1.0f / 128.0f) + 1e-5f);
        int grow = row0 + r_;
        if (grow < M) {
            float4 o4;
            o4.x = fmaxf(d0 * rstd * gv.x + ev.x, 0.f);
            o4.y = fmaxf(d1 * rstd * gv.y + ev.y, 0.f);
            o4.z = fmaxf(d2 * rstd * gv.z + ev.z, 0.f);
            o4.w = fmaxf(d3 * rstd * gv.w + ev.w, 0.f);
            *reinterpret_cast<float4*>(C + (size_t)grow * D128 + lane * 4) = o4;
        }
    }
}

// ---------------------------------------------------------------------------
// CSR construction
// ---------------------------------------------------------------------------
__global__ void hist_kernel(const int* __restrict__ dst, int E, int* __restrict__ cnt)
{
    int e = blockIdx.x * blockDim.x + threadIdx.x;
    if (e < E) atomicAdd(&cnt[dst[e]], 1);
}

__global__ __launch_bounds__(1024)
void scan1_kernel(const int* __restrict__ cnt, int* __restrict__ off,
                  int* __restrict__ bsum, int n)
{
    __shared__ int ws[32];
    const int tid = threadIdx.x, lane = tid & 31, wid = tid >> 5;
    int i = blockIdx.x * 1024 + tid;
    int v = (i < n) ? cnt[i] : 0;
    int x = v;
    #pragma unroll
    for (int o = 1; o < 32; o <<= 1) {
        int y = __shfl_up_sync(0xFFFFFFFFu, x, o);
        if (lane >= o) x += y;
    }
    if (lane == 31) ws[wid] = x;
    __syncthreads();
    if (wid == 0) {
        int w = ws[lane];
        #pragma unroll
        for (int o = 1; o < 32; o <<= 1) {
            int y = __shfl_up_sync(0xFFFFFFFFu, w, o);
            if (lane >= o) w += y;
        }
        ws[lane] = w;
    }
    __syncthreads();
    int excl = ((wid == 0) ? 0 : ws[wid - 1]) + x - v;
    if (i < n) off[i] = excl;
    if (tid == 0) bsum[blockIdx.x] = ws[31];
}

__global__ void scan2_kernel(int* __restrict__ bsum, int nb)
{
    __shared__ int s[64];
    int l = threadIdx.x;
    s[l] = (l < nb) ? bsum[l] : 0;
    __syncthreads();
    #pragma unroll
    for (int o = 1; o < 64; o <<= 1) {
        int t = (l >= o) ? s[l - o] : 0;
        __syncthreads();
        s[l] += t;
        __syncthreads();
    }
    if (l < nb) bsum[l] = (l > 0) ? s[l - 1] : 0;
}

__global__ void scan3_kernel(int* __restrict__ off, const int* __restrict__ bsum,
                             int n, int E)
{
    int i = blockIdx.x * blockDim.x + threadIdx.x;
    if (i < n) off[i] += bsum[i >> 10];
    if (i == 0) off[n] = E;
}

__global__ void fill_kernel(const int* __restrict__ src, const int* __restrict__ dst,
                            const float* __restrict__ ea, int E,
                            const int* __restrict__ off, int* __restrict__ cur,
                            int2* __restrict__ edge)
{
    int e = blockIdx.x * blockDim.x + threadIdx.x;
    if (e >= E) return;
    int d = dst[e];
    int pos = off[d] + atomicAdd(&cur[d], 1);
    edge[pos] = make_int2(src[e], __float_as_int(ea[e]));
}

extern "C" void kernel_launch(void* const* d_in, const int* in_sizes, int n_in,
                              void* d_out, int out_size)
{
    const float* x_a   = (const float*)d_in[0];
    const float* x_b   = (const float*)d_in[1];
    const int*   ei_ab = (const int*)  d_in[2];
    const float* ea_ab = (const float*)d_in[3];
    const int*   ei_ba = (const int*)  d_in[4];
    const float* ea_ba = (const float*)d_in[5];
    const float* w1_ab = (const float*)d_in[6];
    const float* b1_ab = (const float*)d_in[7];
    const float* w2_ab = (const float*)d_in[8];
    const float* b2_ab = (const float*)d_in[9];
    const float* w1_ba = (const float*)d_in[10];
    const float* b1_ba = (const float*)d_in[11];
    const float* w2_ba = (const float*)d_in[12];
    const float* b2_ba = (const float*)d_in[13];
    const float* wu_a  = (const float*)d_in[14];
    const float* bu_a  = (const float*)d_in[15];
    const float* g_a   = (const float*)d_in[16];
    const float* be_a  = (const float*)d_in[17];
    const float* wu_b  = (const float*)d_in[18];
    const float* bu_b  = (const float*)d_in[19];
    const float* g_b   = (const float*)d_in[20];
    const float* be_b  = (const float*)d_in[21];

    const int NA   = in_sizes[0] / D128;
    const int NB   = in_sizes[1] / D128;
    const int E_ab = in_sizes[3];
    const int E_ba = in_sizes[5];

    float *T0, *T1;
    int *cnt0, *cnt1, *off0, *off1, *bs0, *bs1;
    int2 *ed0, *ed1;
    cudaGetSymbolAddress((void**)&T0, g_T0);
    cudaGetSymbolAddress((void**)&T1, g_T1);
    { void* p; cudaGetSymbolAddress(&p, g_cnt);  cnt0 = (int*)p;  cnt1 = cnt0 + MAXN; }
    { void* p; cudaGetSymbolAddress(&p, g_off);  off0 = (int*)p;  off1 = off0 + (MAXN + 1); }
    { void* p; cudaGetSymbolAddress(&p, g_bsum); bs0  = (int*)p;  bs1  = bs0 + 64; }
    { void* p; cudaGetSymbolAddress(&p, g_edge); ed0  = (int2*)p; ed1  = ed0 + MAXE; }

    float* out   = (float*)d_out;
    float* out_a = out;
    float* out_b = out + (size_t)NA * D128;

    // Lazy one-time setup (first call happens BEFORE graph capture).
    static cudaStream_t s1 = nullptr, s2 = nullptr, s3 = nullptr;
    static cudaEvent_t evRoot, evPre, evA, evB;
    if (!s1) {
        cudaStreamCreateWithFlags(&s1, cudaStreamNonBlocking);
        cudaStreamCreateWithFlags(&s2, cudaStreamNonBlocking);
        cudaStreamCreateWithFlags(&s3, cudaStreamNonBlocking);
        cudaEventCreateWithFlags(&evRoot, cudaEventDisableTiming);
        cudaEventCreateWithFlags(&evPre,  cudaEventDisableTiming);
        cudaEventCreateWithFlags(&evA,    cudaEventDisableTiming);
        cudaEventCreateWithFlags(&evB,    cudaEventDisableTiming);
        cudaFuncSetAttribute(mlp_fused,     cudaFuncAttributeMaxDynamicSharedMemorySize, (int)MLP_SMEM);
        cudaFuncSetAttribute(gather_gemm_ln,cudaFuncAttributeMaxDynamicSharedMemorySize, (int)GLN_SMEM);
    }

    const int blkA  = (NA + 127) / 128;
    const int blkB  = (NB + 127) / 128;
    const int eblkA = (E_ab + 255) / 256;
    const int eblkB = (E_ba + 255) / 256;
    const int nbB   = (NB + 1023) / 1024;
    const int nbA   = (NA + 1023) / 1024;

    // Fork from capture stream (0).
    cudaEventRecord(evRoot, 0);
    cudaStreamWaitEvent(s1, evRoot, 0);
    cudaStreamWaitEvent(s2, evRoot, 0);
    cudaStreamWaitEvent(s3, evRoot, 0);

    // --- s1: CSR preprocessing (both directions) ---
    cudaMemsetAsync(cnt0, 0, sizeof(int) * MAXN * 2, s1);
    hist_kernel<<<eblkA, 256, 0, s1>>>(ei_ab + E_ab, E_ab, cnt0);
    hist_kernel<<<eblkB, 256, 0, s1>>>(ei_ba + E_ba, E_ba, cnt1);
    scan1_kernel<<<nbB, 1024, 0, s1>>>(cnt0, off0, bs0, NB);
    scan1_kernel<<<nbA, 1024, 0, s1>>>(cnt1, off1, bs1, NA);
    scan2_kernel<<<1, 64, 0, s1>>>(bs0, nbB);
    scan2_kernel<<<1, 64, 0, s1>>>(bs1, nbA);
    scan3_kernel<<<nbB, 1024, 0, s1>>>(off0, bs0, NB, E_ab);
    scan3_kernel<<<nbA, 1024, 0, s1>>>(off1, bs1, NA, E_ba);
    cudaMemsetAsync(cnt0, 0, sizeof(int) * MAXN * 2, s1);
    fill_kernel<<<eblkA, 256, 0, s1>>>(ei_ab, ei_ab + E_ab, ea_ab, E_ab, off0, cnt0, ed0);
    fill_kernel<<<eblkB, 256, 0, s1>>>(ei_ba, ei_ba + E_ba, ea_ba, E_ba, off1, cnt1, ed1);
    cudaEventRecord(evPre, s1);

    // --- s2: a->b chain -> out_b ---
    mlp_fused<<<blkA, 512, MLP_SMEM, s2>>>(x_a, w1_ab, b1_ab, w2_ab, b2_ab, T0, NA);
    cudaStreamWaitEvent(s2, evPre, 0);
    gather_gemm_ln<<<blkB, 512, GLN_SMEM, s2>>>(T0, x_b, off0, ed0,
                                                wu_b, bu_b, g_b, be_b, out_b, NB);
    cudaEventRecord(evB, s2);

    // --- s3: b->a chain -> out_a ---
    mlp_fused<<<blkB, 512, MLP_SMEM, s3>>>(x_b, w1_ba, b1_ba, w2_ba, b2_ba, T1, NB);
    cudaStreamWaitEvent(s3, evPre, 0);
    gather_gemm_ln<<<blkA, 512, GLN_SMEM, s3>>>(T1, x_a, off1, ed1,
                                                wu_a, bu_a, g_a, be_a, out_a, NA);
    cudaEventRecord(evA, s3);

    // Join back to capture stream.
    cudaStreamWaitEvent(0, evA, 0);
    cudaStreamWaitEvent(0, evB, 0);
}

// round 11
// speedup vs baseline: 1.3698x; 1.3698x over previous
#include <cuda_runtime.h>
#include <cstdint>

// ---------------------------------------------------------------------------
// HeteroGraphConv, D=128.
//   CSR preprocess (side stream): hist -> 3-stage scan -> fill (int2 edges)
//   per direction (own stream):
//     T = (relu(x@w1+b1))@w2+b2   (PERSISTENT fused tf32 mma kernel:
//                                  W1+W2 staged once, loop over row tiles,
//                                  H overwrites X tile in smem)
//     aggr[d] = x[d] + sum w_e*T[src_e]   (CSR gather, warp/row, high occ)
//     out = relu(LN(aggr@wu+bu)*g+be)     (tf32 GEMM + fused LN, in-place)
// ---------------------------------------------------------------------------

#define D128 128
#define MAXN 50176
#define MAXE 450048

__device__ float g_T0[MAXN * D128];
__device__ float g_T1[MAXN * D128];
__device__ int   g_cnt [2][MAXN];
__device__ int   g_off [2][MAXN + 1];
__device__ int   g_bsum[2][64];
__device__ int2  g_edge[2][MAXE];

__device__ __forceinline__ unsigned f2tf32(float f) {
    unsigned r;
    asm("cvt.rna.tf32.f32 %0, %1;" : "=r"(r) : "f"(f));
    return r;
}
__device__ __forceinline__ float tf32f(float f) { return __uint_as_float(f2tf32(f)); }

#define TS 132
#define TILE (128 * TS)
#define MLP_SMEM (3 * TILE * sizeof(float))   // W1 | W2 | X/H  = 202,752 B

// ---------------------------------------------------------------------------
// Shared MMA mainloop: 16 warps (4x4), warp (wm,wn) owns 32x32 output tile.
// ---------------------------------------------------------------------------
__device__ __forceinline__ void mma_mainloop_128(
    const float* Am, const float* Bm,
    int wm, int wn, int g, int t, float acc[2][4][4])
{
    #pragma unroll
    for (int ks = 0; ks < 16; ks++) {
        const int k0 = ks * 8;
        unsigned a[2][4];
        #pragma unroll
        for (int mf = 0; mf < 2; mf++) {
            const float* ap = Am + (wm * 32 + mf * 16 + g) * TS + k0 + t;
            a[mf][0] = __float_as_uint(ap[0]);
            a[mf][1] = __float_as_uint(ap[8 * TS]);
            a[mf][2] = __float_as_uint(ap[4]);
            a[mf][3] = __float_as_uint(ap[8 * TS + 4]);
        }
        unsigned b[4][2];
        #pragma unroll
        for (int nf = 0; nf < 4; nf++) {
            const float* wp = Bm + (k0 + t) * TS + wn * 32 + nf * 8 + g;
            b[nf][0] = __float_as_uint(wp[0]);
            b[nf][1] = __float_as_uint(wp[4 * TS]);
        }
        #pragma unroll
        for (int mf = 0; mf < 2; mf++)
            #pragma unroll
            for (int nf = 0; nf < 4; nf++)
                asm volatile(
                    "mma.sync.aligned.m16n8k8.row.col.f32.tf32.tf32.f32 "
                    "{%0,%1,%2,%3}, {%4,%5,%6,%7}, {%8,%9}, {%0,%1,%2,%3};"
                    : "+f"(acc[mf][nf][0]), "+f"(acc[mf][nf][1]),
                      "+f"(acc[mf][nf][2]), "+f"(acc[mf][nf][3])
                    : "r"(a[mf][0]), "r"(a[mf][1]), "r"(a[mf][2]), "r"(a[mf][3]),
                      "r"(b[nf][0]), "r"(b[nf][1]));
    }
}

// ---------------------------------------------------------------------------
// Persistent fused edge-MLP: weights resident, loop over 128-row tiles.
// smem: W1s[128][TS] | W2s[128][TS] | X[128][TS] (H written in place over X)
// ---------------------------------------------------------------------------
__global__ __launch_bounds__(512)
void mlp_persist(const float* __restrict__ A,
                 const float* __restrict__ W1, const float* __restrict__ b1,
                 const float* __restrict__ W2, const float* __restrict__ b2,
                 float* __restrict__ T, int M, int numTiles)
{
    extern __shared__ float smem[];
    float* W1s = smem;
    float* W2s = smem + TILE;
    float* X   = smem + 2 * TILE;

    const int tid  = threadIdx.x;
    const int lane = tid & 31;
    const int wid  = tid >> 5;
    const int wm   = wid >> 2;
    const int wn   = wid & 3;
    const int g    = lane >> 2;
    const int t    = lane & 3;

    // Stage W1 and W2 once (tf32).
    #pragma unroll
    for (int i = 0; i < 8; i++) {
        int idx = tid + i * 512, r = idx >> 5, c = (idx & 31) * 4;
        float4 w1 = *reinterpret_cast<const float4*>(W1 + (size_t)r * D128 + c);
        float4 w2 = *reinterpret_cast<const float4*>(W2 + (size_t)r * D128 + c);
        *reinterpret_cast<float4*>(W1s + r * TS + c) =
            make_float4(tf32f(w1.x), tf32f(w1.y), tf32f(w1.z), tf32f(w1.w));
        *reinterpret_cast<float4*>(W2s + r * TS + c) =
            make_float4(tf32f(w2.x), tf32f(w2.y), tf32f(w2.z), tf32f(w2.w));
    }
    __syncthreads();

    for (int tile = blockIdx.x; tile < numTiles; tile += gridDim.x) {
        const int row0 = tile * 128;

        // Stage X tile (tf32, bounds-checked).
        #pragma unroll
        for (int i = 0; i < 8; i++) {
            int idx = tid + i * 512, r = idx >> 5, c = (idx & 31) * 4;
            int gr = row0 + r;
            float4 v = (gr < M)
                ? *reinterpret_cast<const float4*>(A + (size_t)gr * D128 + c)
                : make_float4(0.f, 0.f, 0.f, 0.f);
            *reinterpret_cast<float4*>(X + r * TS + c) =
                make_float4(tf32f(v.x), tf32f(v.y), tf32f(v.z), tf32f(v.w));
        }
        __syncthreads();

        float acc[2][4][4];
        #pragma unroll
        for (int mf = 0; mf < 2; mf++)
            #pragma unroll
            for (int nf = 0; nf < 4; nf++)
                #pragma unroll
                for (int j = 0; j < 4; j++) acc[mf][nf][j] = 0.0f;

        // Phase 1: H = relu(X@W1 + b1)
        mma_mainloop_128(X, W1s, wm, wn, g, t, acc);
        __syncthreads();   // all warps done reading X; safe to overwrite

        #pragma unroll
        for (int mf = 0; mf < 2; mf++) {
            int r_ = wm * 32 + mf * 16 + g;
            #pragma unroll
            for (int nf = 0; nf < 4; nf++) {
                int col = wn * 32 + nf * 8 + 2 * t;
                float b0 = b1[col], b1v = b1[col + 1];
                X[r_ * TS + col]           = tf32f(fmaxf(acc[mf][nf][0] + b0,  0.f));
                X[r_ * TS + col + 1]       = tf32f(fmaxf(acc[mf][nf][1] + b1v, 0.f));
                X[(r_ + 8) * TS + col]     = tf32f(fmaxf(acc[mf][nf][2] + b0,  0.f));
                X[(r_ + 8) * TS + col + 1] = tf32f(fmaxf(acc[mf][nf][3] + b1v, 0.f));
                acc[mf][nf][0] = acc[mf][nf][1] = acc[mf][nf][2] = acc[mf][nf][3] = 0.f;
            }
        }
        __syncthreads();

        // Phase 2: T = H@W2 + b2
        mma_mainloop_128(X, W2s, wm, wn, g, t, acc);
        #pragma unroll
        for (int mf = 0; mf < 2; mf++) {
            int r_ = row0 + wm * 32 + mf * 16 + g;
            #pragma unroll
            for (int nf = 0; nf < 4; nf++) {
                int col = wn * 32 + nf * 8 + 2 * t;
                float b0 = b2[col], b1v = b2[col + 1];
                float2 v0, v1;
                v0.x = acc[mf][nf][0] + b0; v0.y = acc[mf][nf][1] + b1v;
                v1.x = acc[mf][nf][2] + b0; v1.y = acc[mf][nf][3] + b1v;
                if (r_ < M)
                    *reinterpret_cast<float2*>(T + (size_t)r_ * D128 + col) = v0;
                if (r_ + 8 < M)
                    *reinterpret_cast<float2*>(T + (size_t)(r_ + 8) * D128 + col) = v1;
            }
        }
        __syncthreads();   // mainloop-2 readers done before next X overwrite
    }
}

// ---------------------------------------------------------------------------
// Node-update GEMM with fused bias + LayerNorm + ReLU (in-place safe).
// 512 threads, 16 warps (32x32 per warp), double-buffered k-chunks. (R9 ver.)
// ---------------------------------------------------------------------------
#define BKC 32
#define AS_STRIDE 36
#define WS_STRIDE 132
#define AS_SIZE (128 * AS_STRIDE)
#define WS_SIZE (BKC * WS_STRIDE)
#define BUF_SIZE (AS_SIZE + WS_SIZE)
#define LN_SMEM (2 * BUF_SIZE * sizeof(float))

__global__ __launch_bounds__(512)
void gemm_ln(const float* __restrict__ A,
             const float* __restrict__ W,
             const float* __restrict__ bias,
             const float* __restrict__ gamma,
             const float* __restrict__ beta,
             float* __restrict__ C,
             int M)
{
    extern __shared__ float smem[];

    const int tid  = threadIdx.x;
    const int lane = tid & 31;
    const int wid  = tid >> 5;
    const int wm   = wid >> 2;
    const int wn   = wid & 3;
    const int g    = lane >> 2;
    const int t    = lane & 3;
    const int row0 = blockIdx.x * 128;

    float acc[2][4][4];
    #pragma unroll
    for (int mf = 0; mf < 2; mf++)
        #pragma unroll
        for (int nf = 0; nf < 4; nf++)
            #pragma unroll
            for (int j = 0; j < 4; j++) acc[mf][nf][j] = 0.0f;

    float4 aLd[2], wLd[2];

    auto ldg_chunk = [&](int kc) {
        #pragma unroll
        for (int i = 0; i < 2; i++) {
            int idx = tid + i * 512;
            int r = idx >> 3, c = (idx & 7) * 4;
            int gr = row0 + r;
            aLd[i] = (gr < M)
                ? *reinterpret_cast<const float4*>(A + (size_t)gr * D128 + kc + c)
                : make_float4(0.f, 0.f, 0.f, 0.f);
        }
        #pragma unroll
        for (int i = 0; i < 2; i++) {
            int idx = tid + i * 512;
            int r = idx >> 5, c = (idx & 31) * 4;
            wLd[i] = *reinterpret_cast<const float4*>(W + (size_t)(kc + r) * D128 + c);
        }
    };
    auto sts_chunk = [&](int b) {
        float* as = smem + b * BUF_SIZE;
        float* ws = as + AS_SIZE;
        #pragma unroll
        for (int i = 0; i < 2; i++) {
            int idx = tid + i * 512;
            int r = idx >> 3, c = (idx & 7) * 4;
            *reinterpret_cast<float4*>(as + r * AS_STRIDE + c) =
                make_float4(tf32f(aLd[i].x), tf32f(aLd[i].y),
                            tf32f(aLd[i].z), tf32f(aLd[i].w));
        }
        #pragma unroll
        for (int i = 0; i < 2; i++) {
            int idx = tid + i * 512;
            int r = idx >> 5, c = (idx & 31) * 4;
            *reinterpret_cast<float4*>(ws + r * WS_STRIDE + c) =
                make_float4(tf32f(wLd[i].x), tf32f(wLd[i].y),
                            tf32f(wLd[i].z), tf32f(wLd[i].w));
        }
    };

    ldg_chunk(0);
    sts_chunk(0);
    __syncthreads();

    #pragma unroll
    for (int c = 0; c < 4; c++) {
        if (c < 3) ldg_chunk((c + 1) * BKC);
        const float* as = smem + (c & 1) * BUF_SIZE;
        const float* ws = as + AS_SIZE;
        #pragma unroll
        for (int ks = 0; ks < 4; ks++) {
            const int k0 = ks * 8;
            unsigned a[2][4];
            #pragma unroll
            for (int mf = 0; mf < 2; mf++) {
                const float* ap = as + (wm * 32 + mf * 16 + g) * AS_STRIDE + k0 + t;
                a[mf][0] = __float_as_uint(ap[0]);
                a[mf][1] = __float_as_uint(ap[8 * AS_STRIDE]);
                a[mf][2] = __float_as_uint(ap[4]);
                a[mf][3] = __float_as_uint(ap[8 * AS_STRIDE + 4]);
            }
            unsigned b[4][2];
            #pragma unroll
            for (int nf = 0; nf < 4; nf++) {
                const float* wp = ws + (k0 + t) * WS_STRIDE + wn * 32 + nf * 8 + g;
                b[nf][0] = __float_as_uint(wp[0]);
                b[nf][1] = __float_as_uint(wp[4 * WS_STRIDE]);
            }
            #pragma unroll
            for (int mf = 0; mf < 2; mf++)
                #pragma unroll
                for (int nf = 0; nf < 4; nf++)
                    asm volatile(
                        "mma.sync.aligned.m16n8k8.row.col.f32.tf32.tf32.f32 "
                        "{%0,%1,%2,%3}, {%4,%5,%6,%7}, {%8,%9}, {%0,%1,%2,%3};"
                        : "+f"(acc[mf][nf][0]), "+f"(acc[mf][nf][1]),
                          "+f"(acc[mf][nf][2]), "+f"(acc[mf][nf][3])
                        : "r"(a[mf][0]), "r"(a[mf][1]), "r"(a[mf][2]), "r"(a[mf][3]),
                          "r"(b[nf][0]), "r"(b[nf][1]));
        }
        __syncthreads();
        if (c < 3) {
            sts_chunk((c + 1) & 1);
            __syncthreads();
        }
    }

    // LN epilogue via smem transpose
    float* S = smem;   // [128][132]
    #pragma unroll
    for (int mf = 0; mf < 2; mf++) {
        int r_ = wm * 32 + mf * 16 + g;
        #pragma unroll
        for (int nf = 0; nf < 4; nf++) {
            int col = wn * 32 + nf * 8 + 2 * t;
            S[r_ * 132 + col]           = acc[mf][nf][0];
            S[r_ * 132 + col + 1]       = acc[mf][nf][1];
            S[(r_ + 8) * 132 + col]     = acc[mf][nf][2];
            S[(r_ + 8) * 132 + col + 1] = acc[mf][nf][3];
        }
    }
    __syncthreads();

    float4 bv = *reinterpret_cast<const float4*>(bias  + lane * 4);
    float4 gv = *reinterpret_cast<const float4*>(gamma + lane * 4);
    float4 ev = *reinterpret_cast<const float4*>(beta  + lane * 4);

    #pragma unroll
    for (int rr = 0; rr < 8; rr++) {
        int r_ = wid * 8 + rr;
        float4 h = *reinterpret_cast<const float4*>(S + r_ * 132 + lane * 4);
        h.x += bv.x; h.y += bv.y; h.z += bv.z; h.w += bv.w;
        float s = h.x + h.y + h.z + h.w;
        #pragma unroll
        for (int o = 16; o > 0; o >>= 1) s += __shfl_xor_sync(0xFFFFFFFFu, s, o);
        float mu = s * (1.0f / 128.0f);
        float d0 = h.x - mu, d1 = h.y - mu, d2 = h.z - mu, d3 = h.w - mu;
        float q = d0 * d0 + d1 * d1 + d2 * d2 + d3 * d3;
        #pragma unroll
        for (int o = 16; o > 0; o >>= 1) q += __shfl_xor_sync(0xFFFFFFFFu, q, o);
        float rstd = rsqrtf(q * (1.0f / 128.0f) + 1e-5f);
        int grow = row0 + r_;
        if (grow < M) {
            float4 o4;
            o4.x = fmaxf(d0 * rstd * gv.x + ev.x, 0.f);
            o4.y = fmaxf(d1 * rstd * gv.y + ev.y, 0.f);
            o4.z = fmaxf(d2 * rstd * gv.z + ev.z, 0.f);
            o4.w = fmaxf(d3 * rstd * gv.w + ev.w, 0.f);
            *reinterpret_cast<float4*>(C + (size_t)grow * D128 + lane * 4) = o4;
        }
    }
}

// ---------------------------------------------------------------------------
// CSR construction
// ---------------------------------------------------------------------------
__global__ void hist_kernel(const int* __restrict__ dst, int E, int* __restrict__ cnt)
{
    int e = blockIdx.x * blockDim.x + threadIdx.x;
    if (e < E) atomicAdd(&cnt[dst[e]], 1);
}

__global__ __launch_bounds__(1024)
void scan1_kernel(const int* __restrict__ cnt, int* __restrict__ off,
                  int* __restrict__ bsum, int n)
{
    __shared__ int ws[32];
    const int tid = threadIdx.x, lane = tid & 31, wid = tid >> 5;
    int i = blockIdx.x * 1024 + tid;
    int v = (i < n) ? cnt[i] : 0;
    int x = v;
    #pragma unroll
    for (int o = 1; o < 32; o <<= 1) {
        int y = __shfl_up_sync(0xFFFFFFFFu, x, o);
        if (lane >= o) x += y;
    }
    if (lane == 31) ws[wid] = x;
    __syncthreads();
    if (wid == 0) {
        int w = ws[lane];
        #pragma unroll
        for (int o = 1; o < 32; o <<= 1) {
            int y = __shfl_up_sync(0xFFFFFFFFu, w, o);
            if (lane >= o) w += y;
        }
        ws[lane] = w;
    }
    __syncthreads();
    int excl = ((wid == 0) ? 0 : ws[wid - 1]) + x - v;
    if (i < n) off[i] = excl;
    if (tid == 0) bsum[blockIdx.x] = ws[31];
}

__global__ void scan2_kernel(int* __restrict__ bsum, int nb)
{
    __shared__ int s[64];
    int l = threadIdx.x;
    s[l] = (l < nb) ? bsum[l] : 0;
    __syncthreads();
    #pragma unroll
    for (int o = 1; o < 64; o <<= 1) {
        int t = (l >= o) ? s[l - o] : 0;
        __syncthreads();
        s[l] += t;
        __syncthreads();
    }
    if (l < nb) bsum[l] = (l > 0) ? s[l - 1] : 0;
}

__global__ void scan3_kernel(int* __restrict__ off, const int* __restrict__ bsum,
                             int n, int E)
{
    int i = blockIdx.x * blockDim.x + threadIdx.x;
    if (i < n) off[i] += bsum[i >> 10];
    if (i == 0) off[n] = E;
}

__global__ void fill_kernel(const int* __restrict__ src, const int* __restrict__ dst,
                            const float* __restrict__ ea, int E,
                            const int* __restrict__ off, int* __restrict__ cur,
                            int2* __restrict__ edge)
{
    int e = blockIdx.x * blockDim.x + threadIdx.x;
    if (e >= E) return;
    int d = dst[e];
    int pos = off[d] + atomicAdd(&cur[d], 1);
    edge[pos] = make_int2(src[e], __float_as_int(ea[e]));
}

// ---------------------------------------------------------------------------
// Gather: one warp per dst row; residual folded in via init from x. (R9 ver.)
// ---------------------------------------------------------------------------
__global__ __launch_bounds__(256)
void gather_kernel(const float* __restrict__ T,
                   const float* __restrict__ x,
                   const int* __restrict__ off,
                   const int2* __restrict__ edge,
                   float* __restrict__ aggr,
                   int N)
{
    int w    = (blockIdx.x * blockDim.x + threadIdx.x) >> 5;
    int lane = threadIdx.x & 31;
    if (w >= N) return;

    float4 acc = reinterpret_cast<const float4*>(x + (size_t)w * D128)[lane];

    int j  = __ldg(off + w);
    int s1 = __ldg(off + w + 1);

    for (; j + 1 < s1; j += 2) {
        int2 eA = __ldg(edge + j), eB = __ldg(edge + j + 1);
        float wA = __int_as_float(eA.y), wB = __int_as_float(eB.y);
        float4 vA = reinterpret_cast<const float4*>(T + (size_t)eA.x * D128)[lane];
        float4 vB = reinterpret_cast<const float4*>(T + (size_t)eB.x * D128)[lane];
        acc.x = fmaf(wA, vA.x, acc.x); acc.x = fmaf(wB, vB.x, acc.x);
        acc.y = fmaf(wA, vA.y, acc.y); acc.y = fmaf(wB, vB.y, acc.y);
        acc.z = fmaf(wA, vA.z, acc.z); acc.z = fmaf(wB, vB.z, acc.z);
        acc.w = fmaf(wA, vA.w, acc.w); acc.w = fmaf(wB, vB.w, acc.w);
    }
    if (j < s1) {
        int2 eA = __ldg(edge + j);
        float wA = __int_as_float(eA.y);
        float4 vA = reinterpret_cast<const float4*>(T + (size_t)eA.x * D128)[lane];
        acc.x = fmaf(wA, vA.x, acc.x);
        acc.y = fmaf(wA, vA.y, acc.y);
        acc.z = fmaf(wA, vA.z, acc.z);
        acc.w = fmaf(wA, vA.w, acc.w);
    }

    reinterpret_cast<float4*>(aggr + (size_t)w * D128)[lane] = acc;
}

extern "C" void kernel_launch(void* const* d_in, const int* in_sizes, int n_in,
                              void* d_out, int out_size)
{
    const float* x_a   = (const float*)d_in[0];
    const float* x_b   = (const float*)d_in[1];
    const int*   ei_ab = (const int*)  d_in[2];
    const float* ea_ab = (const float*)d_in[3];
    const int*   ei_ba = (const int*)  d_in[4];
    const float* ea_ba = (const float*)d_in[5];
    const float* w1_ab = (const float*)d_in[6];
    const float* b1_ab = (const float*)d_in[7];
    const float* w2_ab = (const float*)d_in[8];
    const float* b2_ab = (const float*)d_in[9];
    const float* w1_ba = (const float*)d_in[10];
    const float* b1_ba = (const float*)d_in[11];
    const float* w2_ba = (const float*)d_in[12];
    const float* b2_ba = (const float*)d_in[13];
    const float* wu_a  = (const float*)d_in[14];
    const float* bu_a  = (const float*)d_in[15];
    const float* g_a   = (const float*)d_in[16];
    const float* be_a  = (const float*)d_in[17];
    const float* wu_b  = (const float*)d_in[18];
    const float* bu_b  = (const float*)d_in[19];
    const float* g_b   = (const float*)d_in[20];
    const float* be_b  = (const float*)d_in[21];

    const int NA   = in_sizes[0] / D128;
    const int NB   = in_sizes[1] / D128;
    const int E_ab = in_sizes[3];
    const int E_ba = in_sizes[5];

    float *T0, *T1;
    int *cnt0, *cnt1, *off0, *off1, *bs0, *bs1;
    int2 *ed0, *ed1;
    cudaGetSymbolAddress((void**)&T0, g_T0);
    cudaGetSymbolAddress((void**)&T1, g_T1);
    { void* p; cudaGetSymbolAddress(&p, g_cnt);  cnt0 = (int*)p;  cnt1 = cnt0 + MAXN; }
    { void* p; cudaGetSymbolAddress(&p, g_off);  off0 = (int*)p;  off1 = off0 + (MAXN + 1); }
    { void* p; cudaGetSymbolAddress(&p, g_bsum); bs0  = (int*)p;  bs1  = bs0 + 64; }
    { void* p; cudaGetSymbolAddress(&p, g_edge); ed0  = (int2*)p; ed1  = ed0 + MAXE; }

    float* out    = (float*)d_out;
    float* aggr_a = out;
    float* aggr_b = out + (size_t)NA * D128;

    // Lazy one-time setup (first call happens BEFORE graph capture).
    static cudaStream_t s1 = nullptr, s2 = nullptr, s3 = nullptr;
    static cudaEvent_t evRoot, evPre, evA, evB;
    static int nSM = 148;
    if (!s1) {
        cudaStreamCreateWithFlags(&s1, cudaStreamNonBlocking);
        cudaStreamCreateWithFlags(&s2, cudaStreamNonBlocking);
        cudaStreamCreateWithFlags(&s3, cudaStreamNonBlocking);
        cudaEventCreateWithFlags(&evRoot, cudaEventDisableTiming);
        cudaEventCreateWithFlags(&evPre,  cudaEventDisableTiming);
        cudaEventCreateWithFlags(&evA,    cudaEventDisableTiming);
        cudaEventCreateWithFlags(&evB,    cudaEventDisableTiming);
        cudaFuncSetAttribute(mlp_persist, cudaFuncAttributeMaxDynamicSharedMemorySize, (int)MLP_SMEM);
        cudaFuncSetAttribute(gemm_ln,     cudaFuncAttributeMaxDynamicSharedMemorySize, (int)LN_SMEM);
        cudaDeviceGetAttribute(&nSM, cudaDevAttrMultiProcessorCount, 0);
    }

    const int tilesA = (NA + 127) / 128;
    const int tilesB = (NB + 127) / 128;
    const int gridA  = tilesA < nSM ? tilesA : nSM;
    const int gridB  = tilesB < nSM ? tilesB : nSM;
    const int eblkA  = (E_ab + 255) / 256;
    const int eblkB  = (E_ba + 255) / 256;
    const int nbB    = (NB + 1023) / 1024;
    const int nbA    = (NA + 1023) / 1024;

    // Fork from capture stream (0).
    cudaEventRecord(evRoot, 0);
    cudaStreamWaitEvent(s1, evRoot, 0);
    cudaStreamWaitEvent(s2, evRoot, 0);
    cudaStreamWaitEvent(s3, evRoot, 0);

    // --- s1: CSR preprocessing (both directions) ---
    cudaMemsetAsync(cnt0, 0, sizeof(int) * MAXN * 2, s1);
    hist_kernel<<<eblkA, 256, 0, s1>>>(ei_ab + E_ab, E_ab, cnt0);
    hist_kernel<<<eblkB, 256, 0, s1>>>(ei_ba + E_ba, E_ba, cnt1);
    scan1_kernel<<<nbB, 1024, 0, s1>>>(cnt0, off0, bs0, NB);
    scan1_kernel<<<nbA, 1024, 0, s1>>>(cnt1, off1, bs1, NA);
    scan2_kernel<<<1, 64, 0, s1>>>(bs0, nbB);
    scan2_kernel<<<1, 64, 0, s1>>>(bs1, nbA);
    scan3_kernel<<<nbB, 1024, 0, s1>>>(off0, bs0, NB, E_ab);
    scan3_kernel<<<nbA, 1024, 0, s1>>>(off1, bs1, NA, E_ba);
    cudaMemsetAsync(cnt0, 0, sizeof(int) * MAXN * 2, s1);
    fill_kernel<<<eblkA, 256, 0, s1>>>(ei_ab, ei_ab + E_ab, ea_ab, E_ab, off0, cnt0, ed0);
    fill_kernel<<<eblkB, 256, 0, s1>>>(ei_ba, ei_ba + E_ba, ea_ba, E_ba, off1, cnt1, ed1);
    cudaEventRecord(evPre, s1);

    // --- s2: a->b chain -> out_b ---
    mlp_persist<<<gridA, 512, MLP_SMEM, s2>>>(x_a, w1_ab, b1_ab, w2_ab, b2_ab, T0, NA, tilesA);
    cudaStreamWaitEvent(s2, evPre, 0);
    gather_kernel<<<(NB + 7) / 8, 256, 0, s2>>>(T0, x_b, off0, ed0, aggr_b, NB);
    gemm_ln<<<tilesB, 512, LN_SMEM, s2>>>(aggr_b, wu_b, bu_b, g_b, be_b, aggr_b, NB);
    cudaEventRecord(evB, s2);

    // --- s3: b->a chain -> out_a ---
    mlp_persist<<<gridB, 512, MLP_SMEM, s3>>>(x_b, w1_ba, b1_ba, w2_ba, b2_ba, T1, NB, tilesB);
    cudaStreamWaitEvent(s3, evPre, 0);
    gather_kernel<<<(NA + 7) / 8, 256, 0, s3>>>(T1, x_a, off1, ed1, aggr_a, NA);
    gemm_ln<<<tilesA, 512, LN_SMEM, s3>>>(aggr_a, wu_a, bu_a, g_a, be_a, aggr_a, NA);
    cudaEventRecord(evA, s3);

    // Join back to capture stream.
    cudaStreamWaitEvent(0, evA, 0);
    cudaStreamWaitEvent(0, evB, 0);
}

// round 12
// speedup vs baseline: 1.3790x; 1.0067x over previous
#include <cuda_runtime.h>
#include <cstdint>

// ---------------------------------------------------------------------------
// HeteroGraphConv, D=128.
//   CSR preprocess (side stream): hist -> 3-stage scan -> fill (int2 edges)
//   per direction (own stream):
//     T = (relu(x@w1+b1))@w2+b2   (persistent fused tf32 mma kernel)
//     aggr[d] = x[d] + sum w_e*T[src_e]   (CSR gather, warp/row, high occ)
//     out = relu(LN(aggr@wu+bu)*g+be)     (tf32 GEMM + fused LN, in-place)
//   This round: software-pipelined fragment loads (register double-buffer)
//   in all MMA mainloops.
// ---------------------------------------------------------------------------

#define D128 128
#define MAXN 50176
#define MAXE 450048

__device__ float g_T0[MAXN * D128];
__device__ float g_T1[MAXN * D128];
__device__ int   g_cnt [2][MAXN];
__device__ int   g_off [2][MAXN + 1];
__device__ int   g_bsum[2][64];
__device__ int2  g_edge[2][MAXE];

__device__ __forceinline__ unsigned f2tf32(float f) {
    unsigned r;
    asm("cvt.rna.tf32.f32 %0, %1;" : "=r"(r) : "f"(f));
    return r;
}
__device__ __forceinline__ float tf32f(float f) { return __uint_as_float(f2tf32(f)); }

#define TS 132
#define TILE (128 * TS)
#define MLP_SMEM (3 * TILE * sizeof(float))   // W1 | W2 | X/H  = 202,752 B

// ---------------------------------------------------------------------------
// Fragment load + pipelined MMA mainloop (16 warps, 4x4; 32x32 per warp).
// SA: stride of A tile rows; SB: stride of B tile rows. NKS: k-steps of 8.
// ---------------------------------------------------------------------------
template <int SA, int SB>
__device__ __forceinline__ void load_frags(
    const float* Am, const float* Bm,
    int wm, int wn, int g, int t, int k0,
    unsigned a[2][4], unsigned b[4][2])
{
    #pragma unroll
    for (int mf = 0; mf < 2; mf++) {
        const float* ap = Am + (wm * 32 + mf * 16 + g) * SA + k0 + t;
        a[mf][0] = __float_as_uint(ap[0]);
        a[mf][1] = __float_as_uint(ap[8 * SA]);
        a[mf][2] = __float_as_uint(ap[4]);
        a[mf][3] = __float_as_uint(ap[8 * SA + 4]);
    }
    #pragma unroll
    for (int nf = 0; nf < 4; nf++) {
        const float* wp = Bm + (k0 + t) * SB + wn * 32 + nf * 8 + g;
        b[nf][0] = __float_as_uint(wp[0]);
        b[nf][1] = __float_as_uint(wp[4 * SB]);
    }
}

__device__ __forceinline__ void mma_8(
    const unsigned a[2][4], const unsigned b[4][2], float acc[2][4][4])
{
    #pragma unroll
    for (int mf = 0; mf < 2; mf++)
        #pragma unroll
        for (int nf = 0; nf < 4; nf++)
            asm volatile(
                "mma.sync.aligned.m16n8k8.row.col.f32.tf32.tf32.f32 "
                "{%0,%1,%2,%3}, {%4,%5,%6,%7}, {%8,%9}, {%0,%1,%2,%3};"
                : "+f"(acc[mf][nf][0]), "+f"(acc[mf][nf][1]),
                  "+f"(acc[mf][nf][2]), "+f"(acc[mf][nf][3])
                : "r"(a[mf][0]), "r"(a[mf][1]), "r"(a[mf][2]), "r"(a[mf][3]),
                  "r"(b[nf][0]), "r"(b[nf][1]));
}

template <int SA, int SB, int NKS>
__device__ __forceinline__ void mma_pipe(
    const float* Am, const float* Bm,
    int wm, int wn, int g, int t, float acc[2][4][4])
{
    unsigned a[2][2][4], b[2][4][2];
    load_frags<SA, SB>(Am, Bm, wm, wn, g, t, 0, a[0], b[0]);
    #pragma unroll
    for (int ks = 0; ks < NKS; ks++) {
        const int cur = ks & 1;
        if (ks + 1 < NKS)
            load_frags<SA, SB>(Am, Bm, wm, wn, g, t, (ks + 1) * 8,
                               a[cur ^ 1], b[cur ^ 1]);
        mma_8(a[cur], b[cur], acc);
    }
}

// ---------------------------------------------------------------------------
// Persistent fused edge-MLP: weights resident, loop over 128-row tiles.
// smem: W1s[128][TS] | W2s[128][TS] | X[128][TS] (H written in place over X)
// ---------------------------------------------------------------------------
__global__ __launch_bounds__(512)
void mlp_persist(const float* __restrict__ A,
                 const float* __restrict__ W1, const float* __restrict__ b1,
                 const float* __restrict__ W2, const float* __restrict__ b2,
                 float* __restrict__ T, int M, int numTiles)
{
    extern __shared__ float smem[];
    float* W1s = smem;
    float* W2s = smem + TILE;
    float* X   = smem + 2 * TILE;

    const int tid  = threadIdx.x;
    const int lane = tid & 31;
    const int wid  = tid >> 5;
    const int wm   = wid >> 2;
    const int wn   = wid & 3;
    const int g    = lane >> 2;
    const int t    = lane & 3;

    // Stage W1 and W2 once (tf32).
    #pragma unroll
    for (int i = 0; i < 8; i++) {
        int idx = tid + i * 512, r = idx >> 5, c = (idx & 31) * 4;
        float4 w1 = *reinterpret_cast<const float4*>(W1 + (size_t)r * D128 + c);
        float4 w2 = *reinterpret_cast<const float4*>(W2 + (size_t)r * D128 + c);
        *reinterpret_cast<float4*>(W1s + r * TS + c) =
            make_float4(tf32f(w1.x), tf32f(w1.y), tf32f(w1.z), tf32f(w1.w));
        *reinterpret_cast<float4*>(W2s + r * TS + c) =
            make_float4(tf32f(w2.x), tf32f(w2.y), tf32f(w2.z), tf32f(w2.w));
    }
    __syncthreads();

    for (int tile = blockIdx.x; tile < numTiles; tile += gridDim.x) {
        const int row0 = tile * 128;

        // Stage X tile (tf32, bounds-checked).
        #pragma unroll
        for (int i = 0; i < 8; i++) {
            int idx = tid + i * 512, r = idx >> 5, c = (idx & 31) * 4;
            int gr = row0 + r;
            float4 v = (gr < M)
                ? *reinterpret_cast<const float4*>(A + (size_t)gr * D128 + c)
                : make_float4(0.f, 0.f, 0.f, 0.f);
            *reinterpret_cast<float4*>(X + r * TS + c) =
                make_float4(tf32f(v.x), tf32f(v.y), tf32f(v.z), tf32f(v.w));
        }
        __syncthreads();

        float acc[2][4][4];
        #pragma unroll
        for (int mf = 0; mf < 2; mf++)
            #pragma unroll
            for (int nf = 0; nf < 4; nf++)
                #pragma unroll
                for (int j = 0; j < 4; j++) acc[mf][nf][j] = 0.0f;

        // Phase 1: H = relu(X@W1 + b1)
        mma_pipe<TS, TS, 16>(X, W1s, wm, wn, g, t, acc);
        __syncthreads();   // all warps done reading X; safe to overwrite

        #pragma unroll
        for (int mf = 0; mf < 2; mf++) {
            int r_ = wm * 32 + mf * 16 + g;
            #pragma unroll
            for (int nf = 0; nf < 4; nf++) {
                int col = wn * 32 + nf * 8 + 2 * t;
                float b0 = b1[col], b1v = b1[col + 1];
                X[r_ * TS + col]           = tf32f(fmaxf(acc[mf][nf][0] + b0,  0.f));
                X[r_ * TS + col + 1]       = tf32f(fmaxf(acc[mf][nf][1] + b1v, 0.f));
                X[(r_ + 8) * TS + col]     = tf32f(fmaxf(acc[mf][nf][2] + b0,  0.f));
                X[(r_ + 8) * TS + col + 1] = tf32f(fmaxf(acc[mf][nf][3] + b1v, 0.f));
                acc[mf][nf][0] = acc[mf][nf][1] = acc[mf][nf][2] = acc[mf][nf][3] = 0.f;
            }
        }
        __syncthreads();

        // Phase 2: T = H@W2 + b2
        mma_pipe<TS, TS, 16>(X, W2s, wm, wn, g, t, acc);
        #pragma unroll
        for (int mf = 0; mf < 2; mf++) {
            int r_ = row0 + wm * 32 + mf * 16 + g;
            #pragma unroll
            for (int nf = 0; nf < 4; nf++) {
                int col = wn * 32 + nf * 8 + 2 * t;
                float b0 = b2[col], b1v = b2[col + 1];
                float2 v0, v1;
                v0.x = acc[mf][nf][0] + b0; v0.y = acc[mf][nf][1] + b1v;
                v1.x = acc[mf][nf][2] + b0; v1.y = acc[mf][nf][3] + b1v;
                if (r_ < M)
                    *reinterpret_cast<float2*>(T + (size_t)r_ * D128 + col) = v0;
                if (r_ + 8 < M)
                    *reinterpret_cast<float2*>(T + (size_t)(r_ + 8) * D128 + col) = v1;
            }
        }
        __syncthreads();   // mainloop-2 readers done before next X overwrite
    }
}

// ---------------------------------------------------------------------------
// Node-update GEMM with fused bias + LayerNorm + ReLU (in-place safe).
// 512 threads, 16 warps (32x32 per warp), double-buffered k-chunks.
// ---------------------------------------------------------------------------
#define BKC 32
#define AS_STRIDE 36
#define WS_STRIDE 132
#define AS_SIZE (128 * AS_STRIDE)
#define WS_SIZE (BKC * WS_STRIDE)
#define BUF_SIZE (AS_SIZE + WS_SIZE)
#define LN_SMEM (2 * BUF_SIZE * sizeof(float))

__global__ __launch_bounds__(512)
void gemm_ln(const float* __restrict__ A,
             const float* __restrict__ W,
             const float* __restrict__ bias,
             const float* __restrict__ gamma,
             const float* __restrict__ beta,
             float* __restrict__ C,
             int M)
{
    extern __shared__ float smem[];

    const int tid  = threadIdx.x;
    const int lane = tid & 31;
    const int wid  = tid >> 5;
    const int wm   = wid >> 2;
    const int wn   = wid & 3;
    const int g    = lane >> 2;
    const int t    = lane & 3;
    const int row0 = blockIdx.x * 128;

    float acc[2][4][4];
    #pragma unroll
    for (int mf = 0; mf < 2; mf++)
        #pragma unroll
        for (int nf = 0; nf < 4; nf++)
            #pragma unroll
            for (int j = 0; j < 4; j++) acc[mf][nf][j] = 0.0f;

    float4 aLd[2], wLd[2];

    auto ldg_chunk = [&](int kc) {
        #pragma unroll
        for (int i = 0; i < 2; i++) {
            int idx = tid + i * 512;
            int r = idx >> 3, c = (idx & 7) * 4;
            int gr = row0 + r;
            aLd[i] = (gr < M)
                ? *reinterpret_cast<const float4*>(A + (size_t)gr * D128 + kc + c)
                : make_float4(0.f, 0.f, 0.f, 0.f);
        }
        #pragma unroll
        for (int i = 0; i < 2; i++) {
            int idx = tid + i * 512;
            int r = idx >> 5, c = (idx & 31) * 4;
            wLd[i] = *reinterpret_cast<const float4*>(W + (size_t)(kc + r) * D128 + c);
        }
    };
    auto sts_chunk = [&](int b) {
        float* as = smem + b * BUF_SIZE;
        float* ws = as + AS_SIZE;
        #pragma unroll
        for (int i = 0; i < 2; i++) {
            int idx = tid + i * 512;
            int r = idx >> 3, c = (idx & 7) * 4;
            *reinterpret_cast<float4*>(as + r * AS_STRIDE + c) =
                make_float4(tf32f(aLd[i].x), tf32f(aLd[i].y),
                            tf32f(aLd[i].z), tf32f(aLd[i].w));
        }
        #pragma unroll
        for (int i = 0; i < 2; i++) {
            int idx = tid + i * 512;
            int r = idx >> 5, c = (idx & 31) * 4;
            *reinterpret_cast<float4*>(ws + r * WS_STRIDE + c) =
                make_float4(tf32f(wLd[i].x), tf32f(wLd[i].y),
                            tf32f(wLd[i].z), tf32f(wLd[i].w));
        }
    };

    ldg_chunk(0);
    sts_chunk(0);
    __syncthreads();

    #pragma unroll
    for (int c = 0; c < 4; c++) {
        if (c < 3) ldg_chunk((c + 1) * BKC);
        const float* as = smem + (c & 1) * BUF_SIZE;
        const float* ws = as + AS_SIZE;
        mma_pipe<AS_STRIDE, WS_STRIDE, 4>(as, ws, wm, wn, g, t, acc);
        __syncthreads();
        if (c < 3) {
            sts_chunk((c + 1) & 1);
            __syncthreads();
        }
    }

    // LN epilogue via smem transpose
    float* S = smem;   // [128][132]
    #pragma unroll
    for (int mf = 0; mf < 2; mf++) {
        int r_ = wm * 32 + mf * 16 + g;
        #pragma unroll
        for (int nf = 0; nf < 4; nf++) {
            int col = wn * 32 + nf * 8 + 2 * t;
            S[r_ * 132 + col]           = acc[mf][nf][0];
            S[r_ * 132 + col + 1]       = acc[mf][nf][1];
            S[(r_ + 8) * 132 + col]     = acc[mf][nf][2];
            S[(r_ + 8) * 132 + col + 1] = acc[mf][nf][3];
        }
    }
    __syncthreads();

    float4 bv = *reinterpret_cast<const float4*>(bias  + lane * 4);
    float4 gv = *reinterpret_cast<const float4*>(gamma + lane * 4);
    float4 ev = *reinterpret_cast<const float4*>(beta  + lane * 4);

    #pragma unroll
    for (int rr = 0; rr < 8; rr++) {
        int r_ = wid * 8 + rr;
        float4 h = *reinterpret_cast<const float4*>(S + r_ * 132 + lane * 4);
        h.x += bv.x; h.y += bv.y; h.z += bv.z; h.w += bv.w;
        float s = h.x + h.y + h.z + h.w;
        #pragma unroll
        for (int o = 16; o > 0; o >>= 1) s += __shfl_xor_sync(0xFFFFFFFFu, s, o);
        float mu = s * (1.0f / 128.0f);
        float d0 = h.x - mu, d1 = h.y - mu, d2 = h.z - mu, d3 = h.w - mu;
        float q = d0 * d0 + d1 * d1 + d2 * d2 + d3 * d3;
        #pragma unroll
        for (int o = 16; o > 0; o >>= 1) q += __shfl_xor_sync(0xFFFFFFFFu, q, o);
        float rstd = rsqrtf(q * (1.0f / 128.0f) + 1e-5f);
        int grow = row0 + r_;
        if (grow < M) {
            float4 o4;
            o4.x = fmaxf(d0 * rstd * gv.x + ev.x, 0.f);
            o4.y = fmaxf(d1 * rstd * gv.y + ev.y, 0.f);
            o4.z = fmaxf(d2 * rstd * gv.z + ev.z, 0.f);
            o4.w = fmaxf(d3 * rstd * gv.w + ev.w, 0.f);
            *reinterpret_cast<float4*>(C + (size_t)grow * D128 + lane * 4) = o4;
        }
    }
}

// ---------------------------------------------------------------------------
// CSR construction
// ---------------------------------------------------------------------------
__global__ void hist_kernel(const int* __restrict__ dst, int E, int* __restrict__ cnt)
{
    int e = blockIdx.x * blockDim.x + threadIdx.x;
    if (e < E) atomicAdd(&cnt[dst[e]], 1);
}

__global__ __launch_bounds__(1024)
void scan1_kernel(const int* __restrict__ cnt, int* __restrict__ off,
                  int* __restrict__ bsum, int n)
{
    __shared__ int ws[32];
    const int tid = threadIdx.x, lane = tid & 31, wid = tid >> 5;
    int i = blockIdx.x * 1024 + tid;
    int v = (i < n) ? cnt[i] : 0;
    int x = v;
    #pragma unroll
    for (int o = 1; o < 32; o <<= 1) {
        int y = __shfl_up_sync(0xFFFFFFFFu, x, o);
        if (lane >= o) x += y;
    }
    if (lane == 31) ws[wid] = x;
    __syncthreads();
    if (wid == 0) {
        int w = ws[lane];
        #pragma unroll
        for (int o = 1; o < 32; o <<= 1) {
            int y = __shfl_up_sync(0xFFFFFFFFu, w, o);
            if (lane >= o) w += y;
        }
        ws[lane] = w;
    }
    __syncthreads();
    int excl = ((wid == 0) ? 0 : ws[wid - 1]) + x - v;
    if (i < n) off[i] = excl;
    if (tid == 0) bsum[blockIdx.x] = ws[31];
}

__global__ void scan2_kernel(int* __restrict__ bsum, int nb)
{
    __shared__ int s[64];
    int l = threadIdx.x;
    s[l] = (l < nb) ? bsum[l] : 0;
    __syncthreads();
    #pragma unroll
    for (int o = 1; o < 64; o <<= 1) {
        int t = (l >= o) ? s[l - o] : 0;
        __syncthreads();
        s[l] += t;
        __syncthreads();
    }
    if (l < nb) bsum[l] = (l > 0) ? s[l - 1] : 0;
}

__global__ void scan3_kernel(int* __restrict__ off, const int* __restrict__ bsum,
                             int n, int E)
{
    int i = blockIdx.x * blockDim.x + threadIdx.x;
    if (i < n) off[i] += bsum[i >> 10];
    if (i == 0) off[n] = E;
}

__global__ void fill_kernel(const int* __restrict__ src, const int* __restrict__ dst,
                            const float* __restrict__ ea, int E,
                            const int* __restrict__ off, int* __restrict__ cur,
                            int2* __restrict__ edge)
{
    int e = blockIdx.x * blockDim.x + threadIdx.x;
    if (e >= E) return;
    int d = dst[e];
    int pos = off[d] + atomicAdd(&cur[d], 1);
    edge[pos] = make_int2(src[e], __float_as_int(ea[e]));
}

// ---------------------------------------------------------------------------
// Gather: one warp per dst row; residual folded in via init from x.
// ---------------------------------------------------------------------------
__global__ __launch_bounds__(256)
void gather_kernel(const float* __restrict__ T,
                   const float* __restrict__ x,
                   const int* __restrict__ off,
                   const int2* __restrict__ edge,
                   float* __restrict__ aggr,
                   int N)
{
    int w    = (blockIdx.x * blockDim.x + threadIdx.x) >> 5;
    int lane = threadIdx.x & 31;
    if (w >= N) return;

    float4 acc = reinterpret_cast<const float4*>(x + (size_t)w * D128)[lane];

    int j  = __ldg(off + w);
    int s1 = __ldg(off + w + 1);

    for (; j + 1 < s1; j += 2) {
        int2 eA = __ldg(edge + j), eB = __ldg(edge + j + 1);
        float wA = __int_as_float(eA.y), wB = __int_as_float(eB.y);
        float4 vA = reinterpret_cast<const float4*>(T + (size_t)eA.x * D128)[lane];
        float4 vB = reinterpret_cast<const float4*>(T + (size_t)eB.x * D128)[lane];
        acc.x = fmaf(wA, vA.x, acc.x); acc.x = fmaf(wB, vB.x, acc.x);
        acc.y = fmaf(wA, vA.y, acc.y); acc.y = fmaf(wB, vB.y, acc.y);
        acc.z = fmaf(wA, vA.z, acc.z); acc.z = fmaf(wB, vB.z, acc.z);
        acc.w = fmaf(wA, vA.w, acc.w); acc.w = fmaf(wB, vB.w, acc.w);
    }
    if (j < s1) {
        int2 eA = __ldg(edge + j);
        float wA = __int_as_float(eA.y);
        float4 vA = reinterpret_cast<const float4*>(T + (size_t)eA.x * D128)[lane];
        acc.x = fmaf(wA, vA.x, acc.x);
        acc.y = fmaf(wA, vA.y, acc.y);
        acc.z = fmaf(wA, vA.z, acc.z);
        acc.w = fmaf(wA, vA.w, acc.w);
    }

    reinterpret_cast<float4*>(aggr + (size_t)w * D128)[lane] = acc;
}

extern "C" void kernel_launch(void* const* d_in, const int* in_sizes, int n_in,
                              void* d_out, int out_size)
{
    const float* x_a   = (const float*)d_in[0];
    const float* x_b   = (const float*)d_in[1];
    const int*   ei_ab = (const int*)  d_in[2];
    const float* ea_ab = (const float*)d_in[3];
    const int*   ei_ba = (const int*)  d_in[4];
    const float* ea_ba = (const float*)d_in[5];
    const float* w1_ab = (const float*)d_in[6];
    const float* b1_ab = (const float*)d_in[7];
    const float* w2_ab = (const float*)d_in[8];
    const float* b2_ab = (const float*)d_in[9];
    const float* w1_ba = (const float*)d_in[10];
    const float* b1_ba = (const float*)d_in[11];
    const float* w2_ba = (const float*)d_in[12];
    const float* b2_ba = (const float*)d_in[13];
    const float* wu_a  = (const float*)d_in[14];
    const float* bu_a  = (const float*)d_in[15];
    const float* g_a   = (const float*)d_in[16];
    const float* be_a  = (const float*)d_in[17];
    const float* wu_b  = (const float*)d_in[18];
    const float* bu_b  = (const float*)d_in[19];
    const float* g_b   = (const float*)d_in[20];
    const float* be_b  = (const float*)d_in[21];

    const int NA   = in_sizes[0] / D128;
    const int NB   = in_sizes[1] / D128;
    const int E_ab = in_sizes[3];
    const int E_ba = in_sizes[5];

    float *T0, *T1;
    int *cnt0, *cnt1, *off0, *off1, *bs0, *bs1;
    int2 *ed0, *ed1;
    cudaGetSymbolAddress((void**)&T0, g_T0);
    cudaGetSymbolAddress((void**)&T1, g_T1);
    { void* p; cudaGetSymbolAddress(&p, g_cnt);  cnt0 = (int*)p;  cnt1 = cnt0 + MAXN; }
    { void* p; cudaGetSymbolAddress(&p, g_off);  off0 = (int*)p;  off1 = off0 + (MAXN + 1); }
    { void* p; cudaGetSymbolAddress(&p, g_bsum); bs0  = (int*)p;  bs1  = bs0 + 64; }
    { void* p; cudaGetSymbolAddress(&p, g_edge); ed0  = (int2*)p; ed1  = ed0 + MAXE; }

    float* out    = (float*)d_out;
    float* aggr_a = out;
    float* aggr_b = out + (size_t)NA * D128;

    // Lazy one-time setup (first call happens BEFORE graph capture).
    static cudaStream_t s1 = nullptr, s2 = nullptr, s3 = nullptr;
    static cudaEvent_t evRoot, evPre, evA, evB;
    static int nSM = 148;
    if (!s1) {
        cudaStreamCreateWithFlags(&s1, cudaStreamNonBlocking);
        cudaStreamCreateWithFlags(&s2, cudaStreamNonBlocking);
        cudaStreamCreateWithFlags(&s3, cudaStreamNonBlocking);
        cudaEventCreateWithFlags(&evRoot, cudaEventDisableTiming);
        cudaEventCreateWithFlags(&evPre,  cudaEventDisableTiming);
        cudaEventCreateWithFlags(&evA,    cudaEventDisableTiming);
        cudaEventCreateWithFlags(&evB,    cudaEventDisableTiming);
        cudaFuncSetAttribute(mlp_persist, cudaFuncAttributeMaxDynamicSharedMemorySize, (int)MLP_SMEM);
        cudaFuncSetAttribute(gemm_ln,     cudaFuncAttributeMaxDynamicSharedMemorySize, (int)LN_SMEM);
        cudaDeviceGetAttribute(&nSM, cudaDevAttrMultiProcessorCount, 0);
    }

    const int tilesA = (NA + 127) / 128;
    const int tilesB = (NB + 127) / 128;
    const int gridA  = tilesA < nSM ? tilesA : nSM;
    const int gridB  = tilesB < nSM ? tilesB : nSM;
    const int eblkA  = (E_ab + 255) / 256;
    const int eblkB  = (E_ba + 255) / 256;
    const int nbB    = (NB + 1023) / 1024;
    const int nbA    = (NA + 1023) / 1024;

    // Fork from capture stream (0).
    cudaEventRecord(evRoot, 0);
    cudaStreamWaitEvent(s1, evRoot, 0);
    cudaStreamWaitEvent(s2, evRoot, 0);
    cudaStreamWaitEvent(s3, evRoot, 0);

    // --- s1: CSR preprocessing (both directions) ---
    cudaMemsetAsync(cnt0, 0, sizeof(int) * MAXN * 2, s1);
    hist_kernel<<<eblkA, 256, 0, s1>>>(ei_ab + E_ab, E_ab, cnt0);
    hist_kernel<<<eblkB, 256, 0, s1>>>(ei_ba + E_ba, E_ba, cnt1);
    scan1_kernel<<<nbB, 1024, 0, s1>>>(cnt0, off0, bs0, NB);
    scan1_kernel<<<nbA, 1024, 0, s1>>>(cnt1, off1, bs1, NA);
    scan2_kernel<<<1, 64, 0, s1>>>(bs0, nbB);
    scan2_kernel<<<1, 64, 0, s1>>>(bs1, nbA);
    scan3_kernel<<<nbB, 1024, 0, s1>>>(off0, bs0, NB, E_ab);
    scan3_kernel<<<nbA, 1024, 0, s1>>>(off1, bs1, NA, E_ba);
    cudaMemsetAsync(cnt0, 0, sizeof(int) * MAXN * 2, s1);
    fill_kernel<<<eblkA, 256, 0, s1>>>(ei_ab, ei_ab + E_ab, ea_ab, E_ab, off0, cnt0, ed0);
    fill_kernel<<<eblkB, 256, 0, s1>>>(ei_ba, ei_ba + E_ba, ea_ba, E_ba, off1, cnt1, ed1);
    cudaEventRecord(evPre, s1);

    // --- s2: a->b chain -> out_b ---
    mlp_persist<<<gridA, 512, MLP_SMEM, s2>>>(x_a, w1_ab, b1_ab, w2_ab, b2_ab, T0, NA, tilesA);
    cudaStreamWaitEvent(s2, evPre, 0);
    gather_kernel<<<(NB + 7) / 8, 256, 0, s2>>>(T0, x_b, off0, ed0, aggr_b, NB);
    gemm_ln<<<tilesB, 512, LN_SMEM, s2>>>(aggr_b, wu_b, bu_b, g_b, be_b, aggr_b, NB);
    cudaEventRecord(evB, s2);

    // --- s3: b->a chain -> out_a ---
    mlp_persist<<<gridB, 512, MLP_SMEM, s3>>>(x_b, w1_ba, b1_ba, w2_ba, b2_ba, T1, NB, tilesB);
    cudaStreamWaitEvent(s3, evPre, 0);
    gather_kernel<<<(NA + 7) / 8, 256, 0, s3>>>(T1, x_a, off1, ed1, aggr_a, NA);
    gemm_ln<<<tilesA, 512, LN_SMEM, s3>>>(aggr_a, wu_a, bu_a, g_a, be_a, aggr_a, NA);
    cudaEventRecord(evA, s3);

    // Join back to capture stream.
    cudaStreamWaitEvent(0, evA, 0);
    cudaStreamWaitEvent(0, evB, 0);
}